// round 6
// baseline (speedup 1.0000x reference)
#include <cuda_runtime.h>

#define B 256
#define S 512
#define T 128
#define STARTT 125
#define STOPT 126
#define TB_PITCH 132  // padded row pitch (floats) for smem transT

// 64MB part-history scratch: hist[b][s][t]
__device__ float g_hist[(size_t)B * S * T];

// ---------------------------------------------------------------------------
// Kernel 1: forward Viterbi max-plus recurrence. One block per batch.
// Thread j holds trans[:, j] packed as 64 f32x2 register pairs.
// Inner loop per 4 "from" states: ld.shared.v2.b64 + 2x add.rn.f32x2 +
// 4x max.f32 (max.f32x2 unsupported by this ptxas).
// ---------------------------------------------------------------------------
__global__ __launch_bounds__(128, 2) void k_forward(
    const float* __restrict__ feats, const float* __restrict__ trans) {
    const int b = blockIdx.x;
    const int j = threadIdx.x;

    // trans column j, packed into 64 x (f32,f32) register pairs
    unsigned long long c2[T / 2];
#pragma unroll
    for (int q = 0; q < T / 2; q++) {
        float lo = trans[(2 * q) * T + j];
        float hi = trans[(2 * q + 1) * T + j];
        asm("mov.b64 %0, {%1, %2};" : "=l"(c2[q]) : "f"(lo), "f"(hi));
    }
    // c[STARTT] = hi half of pair 62 (125 = 2*62+1)
    float cstart;
    {
        float dead;
        asm("mov.b64 {%0, %1}, %2;" : "=f"(dead), "=f"(cstart)
            : "l"(c2[STARTT / 2]));
        (void)dead;
    }

    __shared__ __align__(16) float part[2][T];

    const float* fb = feats + (size_t)b * S * T;
    float* hb = g_hist + (size_t)b * S * T;

    // s = 0: part0 = emit[0] + trans[START][:]
    float p0 = fb[j] + cstart;
    part[0][j] = p0;
    hb[j] = p0;
    // emission prefetch, 2 deep
    float e1 = fb[T + j];
    float e2 = fb[2 * T + j];
    __syncthreads();

    const unsigned sbase0 = (unsigned)__cvta_generic_to_shared(&part[0][0]);

#pragma unroll 1
    for (int s = 1; s < S; s++) {
        float ecur = e1;
        e1 = e2;
        if (s + 2 < S) e2 = fb[(s + 2) * T + j];

        const unsigned pbase =
            sbase0 + (((s - 1) & 1) ? (unsigned)(T * 4) : 0u);

        float m0, m1, m2, m3;
        // q = 0: initialize accumulators with the sums
        asm volatile(
            "{\n\t"
            ".reg .b64 p0, p1, s0, s1;\n\t"
            "ld.shared.v2.b64 {p0, p1}, [%4];\n\t"
            "add.rn.f32x2 s0, p0, %5;\n\t"
            "add.rn.f32x2 s1, p1, %6;\n\t"
            "mov.b64 {%0, %1}, s0;\n\t"
            "mov.b64 {%2, %3}, s1;\n\t"
            "}"
            : "=f"(m0), "=f"(m1), "=f"(m2), "=f"(m3)
            : "r"(pbase), "l"(c2[0]), "l"(c2[1]));
#pragma unroll
        for (int q = 1; q < 32; q++) {
            asm volatile(
                "{\n\t"
                ".reg .b64 p0, p1, s0, s1;\n\t"
                ".reg .f32 a0, a1, a2, a3;\n\t"
                "ld.shared.v2.b64 {p0, p1}, [%4];\n\t"
                "add.rn.f32x2 s0, p0, %5;\n\t"
                "add.rn.f32x2 s1, p1, %6;\n\t"
                "mov.b64 {a0, a1}, s0;\n\t"
                "mov.b64 {a2, a3}, s1;\n\t"
                "max.f32 %0, %0, a0;\n\t"
                "max.f32 %1, %1, a1;\n\t"
                "max.f32 %2, %2, a2;\n\t"
                "max.f32 %3, %3, a3;\n\t"
                "}"
                : "+f"(m0), "+f"(m1), "+f"(m2), "+f"(m3)
                : "r"(pbase + 16u * q), "l"(c2[2 * q]), "l"(c2[2 * q + 1]));
        }
        float np = fmaxf(fmaxf(m0, m1), fmaxf(m2, m3)) + ecur;
        part[s & 1][j] = np;
        hb[s * T + j] = np;
        __syncthreads();
    }
}

// monotonic float -> u32 key (order preserving for finite floats)
__device__ __forceinline__ unsigned fkey(float f) {
    unsigned u = __float_as_uint(f);
    return u ^ ((unsigned)((int)u >> 31) | 0x80000000u);
}

// ---------------------------------------------------------------------------
// Kernel 2: lengths + final pointer + traceback (argmax recompute along path).
// One block per batch, 128 threads; warp 0 runs the serial trace.
// transT transposed directly into padded smem. hist/feats rows prefetched
// 5 deep in a register ring -> memory latency hidden behind the chain.
// ---------------------------------------------------------------------------
__global__ void k_traceback(const float* __restrict__ feats,
                            const float* __restrict__ trans,
                            const void* __restrict__ mask,
                            float* __restrict__ out) {
    const int b = blockIdx.x;
    const int tid = threadIdx.x;

    extern __shared__ float sT[];  // [T][TB_PITCH], sT[j][i] = trans[i][j]
    __shared__ int s_len, s_ptr;
    __shared__ int swsum[4];
    __shared__ float sv[4];
    __shared__ int si[4];

    // transpose trans into padded smem: read coalesced (one-time)
    for (int k = tid; k < T * T; k += 128) {
        int i = k >> 7;    // row of trans
        int jj = k & 127;  // col of trans
        sT[jj * TB_PITCH + i] = trans[k];
    }

    // ---- lengths: robust to mask dtype (first word is a dtype signature,
    // since lengths >= 256 -> mask[0][0..3] all ones) ----
    const unsigned* mw = (const unsigned*)mask;
    unsigned w0 = mw[0];
    int cnt = 0;
    int base = b * S + tid * 4;
    if (w0 == 0x01010101u) {  // 1-byte bool
        const unsigned char* m8 = (const unsigned char*)mask;
        cnt = (m8[base] != 0) + (m8[base + 1] != 0) + (m8[base + 2] != 0) +
              (m8[base + 3] != 0);
    } else if (w0 == 0x3F800000u) {  // float32
        const float* mf = (const float*)mask;
        cnt = (mf[base] != 0.f) + (mf[base + 1] != 0.f) +
              (mf[base + 2] != 0.f) + (mf[base + 3] != 0.f);
    } else if (w0 == 0x3F803F80u || w0 == 0x3C003C00u) {  // bf16 / f16
        const unsigned short* mh = (const unsigned short*)mask;
        cnt = (mh[base] != 0) + (mh[base + 1] != 0) + (mh[base + 2] != 0) +
              (mh[base + 3] != 0);
    } else {  // int32 0/1
        const int* mi = (const int*)mask;
        cnt = (mi[base] != 0) + (mi[base + 1] != 0) + (mi[base + 2] != 0) +
              (mi[base + 3] != 0);
    }
    cnt = __reduce_add_sync(0xffffffffu, cnt);
    if ((tid & 31) == 0) swsum[tid >> 5] = cnt;
    __syncthreads();
    if (tid == 0) s_len = swsum[0] + swsum[1] + swsum[2] + swsum[3];
    __syncthreads();
    const int last_pos = s_len - 1;

    // ---- final pointer: argmax_i(hist[last_pos][i] + trans[i][STOP]) ----
    float v = g_hist[((size_t)b * S + last_pos) * T + tid] +
              sT[STOPT * TB_PITCH + tid];
    int idx = tid;
#pragma unroll
    for (int off = 16; off; off >>= 1) {
        float ov = __shfl_down_sync(0xffffffffu, v, off);
        int oi = __shfl_down_sync(0xffffffffu, idx, off);
        if (ov > v || (ov == v && oi < idx)) { v = ov; idx = oi; }
    }
    if ((tid & 31) == 0) { sv[tid >> 5] = v; si[tid >> 5] = idx; }
    __syncthreads();
    if (tid == 0) {
        float bv = sv[0]; int bi = si[0];
#pragma unroll
        for (int w = 1; w < 4; w++)
            if (sv[w] > bv || (sv[w] == bv && si[w] < bi)) { bv = sv[w]; bi = si[w]; }
        s_ptr = bi;
    }
    __syncthreads();
    const int pointer = s_ptr;
    float* ob = out + b * S;

    // positions past the sequence: zeros (matches zeroed back_points rows)
    for (int s = last_pos + 1 + tid; s < S - 1; s += 128) ob[s] = 0.0f;
    if (tid == 0) {
        ob[S - 1] = (float)pointer;
        ob[last_pos] = (float)pointer;
    }
    if (tid >= 32) return;

    // ---- warp 0: serial traceback with exact argmax recompute ----
    const int l = tid;
    const float4* hist4 =
        reinterpret_cast<const float4*>(g_hist + (size_t)b * S * T);
    const float4* feats4 =
        reinterpret_cast<const float4*>(feats + (size_t)b * S * T);

    int ptr = pointer;
    const int s0 = last_pos - 1;
    if (s0 < 0) return;

#define HROW(ss) hist4[(ss) * 32 + l]
#define EROW(ss) feats4[((ss) + 1) * 32 + l]
    int r1 = s0 - 1 > 0 ? s0 - 1 : 0;
    int r2 = s0 - 2 > 0 ? s0 - 2 : 0;
    int r3 = s0 - 3 > 0 ? s0 - 3 : 0;
    int r4 = s0 - 4 > 0 ? s0 - 4 : 0;
    float4 hb0 = HROW(s0), hb1 = HROW(r1), hb2 = HROW(r2), hb3 = HROW(r3),
           hb4 = HROW(r4);
    float4 eb0 = EROW(s0), eb1 = EROW(r1), eb2 = EROW(r2), eb3 = EROW(r3),
           eb4 = EROW(r4);

    for (int s = s0; s >= 0; --s) {
        float4 h = hb0, er = eb0;
        // shift ring and issue next prefetch immediately (ptr-independent)
        hb0 = hb1; hb1 = hb2; hb2 = hb3; hb3 = hb4;
        eb0 = eb1; eb1 = eb2; eb2 = eb3; eb3 = eb4;
        int sp = s - 5; if (sp < 0) sp = 0;
        hb4 = HROW(sp);
        eb4 = EROW(sp);

        // trans[:, ptr] chunk from padded smem (LDS.128, conflict-free)
        const float4* rowp =
            reinterpret_cast<const float4*>(sT + ptr * TB_PITCH);
        float4 tc = rowp[l];

        // scalar e = feats[b][s+1][ptr] extracted from prefetched row
        int comp = ptr & 3, src = ptr >> 2;
        float cand = (comp == 0) ? er.x
                   : (comp == 1) ? er.y
                   : (comp == 2) ? er.z : er.w;
        float e = __shfl_sync(0xffffffffu, cand, src);

        // exact replication of reference: (part + trans) + e, argmax first-idx
        float q0 = (h.x + tc.x) + e;
        float q1 = (h.y + tc.y) + e;
        float q2 = (h.z + tc.z) + e;
        float q3 = (h.w + tc.w) + e;
        unsigned k0 = fkey(q0), k1 = fkey(q1), k2 = fkey(q2), k3 = fkey(q3);
        unsigned ka = (k0 > k1) ? k0 : k1;
        unsigned kb = (k2 > k3) ? k2 : k3;
        unsigned lm = (ka > kb) ? ka : kb;
        unsigned g = __reduce_max_sync(0xffffffffu, lm);
        unsigned bm = (k0 == g ? 1u : 0u) | (k1 == g ? 2u : 0u) |
                      (k2 == g ? 4u : 0u) | (k3 == g ? 8u : 0u);
        unsigned idxc = bm ? (unsigned)(4 * l + (__ffs((int)bm) - 1))
                           : 0x40000000u;
        ptr = (int)__reduce_min_sync(0xffffffffu, idxc);
        if (l == 0) ob[s] = (float)ptr;
    }
#undef HROW
#undef EROW
}

// ---------------------------------------------------------------------------
extern "C" void kernel_launch(void* const* d_in, const int* in_sizes, int n_in,
                              void* d_out, int out_size) {
    // Identify inputs by element count:
    //   feats 16777216, transitions 16384, mask 131072
    const float* feats = nullptr;
    const void* mask = nullptr;
    const float* trans = nullptr;
    for (int i = 0; i < n_in; i++) {
        int n = in_sizes[i];
        if (n == B * S * T) feats = (const float*)d_in[i];
        else if (n == T * T) trans = (const float*)d_in[i];
        else mask = d_in[i];
    }
    float* out = (float*)d_out;
    (void)out_size;

    const int smem_tb = T * TB_PITCH * sizeof(float);  // 67584 B
    cudaFuncSetAttribute(k_traceback,
                         cudaFuncAttributeMaxDynamicSharedMemorySize, smem_tb);

    k_forward<<<B, T>>>(feats, trans);
    k_traceback<<<B, T, smem_tb>>>(feats, trans, mask, out);
}